// round 1
// baseline (speedup 1.0000x reference)
#include <cuda_runtime.h>
#include <cstdint>

// Problem constants (RecCore: B=8192, D=2048, H=2048, 10 iterations)
#define MB_  8192
#define DD_  2048
#define HH_  2048
#define K3_  (3 * HH_)
#define NITER 10

// Scratch: gi = encoded @ w_ih^T + b_ih  (201 MB), two h ping-pong buffers (134 MB)
__device__ float g_gi[(long long)MB_ * K3_];
__device__ float g_h[2][(long long)MB_ * HH_];

// ---------------- GEMM config ----------------
#define BM 128
#define BN 128
#define BK 32
#define SA 36                         // smem row stride in floats (conflict-free)
#define NTH 512
#define STAGE_FLOATS (BM * SA + 3 * BN * SA)   // 4608 + 13824 = 18432
#define SMEM_BYTES (2 * STAGE_FLOATS * 4)      // 147456

__device__ __forceinline__ uint32_t smem_u32(const void* p) {
    return (uint32_t)__cvta_generic_to_shared(p);
}

__device__ __forceinline__ void cp16(uint32_t s, const float* g) {
    asm volatile("cp.async.cg.shared.global [%0], [%1], 16;\n" :: "r"(s), "l"(g));
}

__device__ __forceinline__ void mma_tf32(float* c, const float* a, float b0, float b1) {
    const uint32_t* A = reinterpret_cast<const uint32_t*>(a);
    uint32_t B0 = __float_as_uint(b0), B1 = __float_as_uint(b1);
    asm volatile(
        "mma.sync.aligned.m16n8k8.row.col.f32.tf32.tf32.f32 "
        "{%0,%1,%2,%3}, {%4,%5,%6,%7}, {%8,%9}, {%0,%1,%2,%3};\n"
        : "+f"(c[0]), "+f"(c[1]), "+f"(c[2]), "+f"(c[3])
        : "r"(A[0]), "r"(A[1]), "r"(A[2]), "r"(A[3]), "r"(B0), "r"(B1));
}

__device__ __forceinline__ float sigf(float x) {
    return 1.0f / (1.0f + __expf(-x));
}

// Fused 3-gate GEMM.
// MODE 0: out[m, g*H + n] = sum_k A[m,k] * W[g*H+n, k] + bias[g*H+n]           (gi)
// MODE 1: GRU step. acc_g = sum_k h[m,k] * W[g*H+n, k];
//         r = sig(gi_r + acc0 + b_r); z = sig(gi_z + acc1 + b_z);
//         n = tanh(gi_n + r*(acc2 + b_n)); out = n + z*(h - n)
template <int MODE>
__global__ void __launch_bounds__(NTH, 1)
gru_gemm(const float* __restrict__ A,     // [8192, 2048]
         const float* __restrict__ W,     // [6144, 2048]
         const float* __restrict__ bias,  // [6144]
         float* __restrict__ out,         // gi (MODE0) or h_out (MODE1)
         const float* __restrict__ gi)    // MODE1 only
{
    extern __shared__ float sm[];
    const int t    = threadIdx.x;
    const int m0   = blockIdx.y * BM;
    const int n0   = blockIdx.x * BN;
    const int K    = DD_;       // == HH_ == 2048 for both GEMMs
    const int lane = t & 31, wid = t >> 5;
    const int wm = (wid >> 2) * 32;
    const int wn = (wid & 3) * 32;
    const int lr = lane >> 2;   // 0..7
    const int lc = lane & 3;    // 0..3

    // copy mapping: A -> 2 float4 per thread, B -> 6 float4 per thread
    const int am = t >> 3;            // 0..63
    const int aq = (t & 7) * 4;       // float offset in k

    float acc[3][2][4][4];
#pragma unroll
    for (int g = 0; g < 3; g++)
#pragma unroll
        for (int i = 0; i < 2; i++)
#pragma unroll
            for (int j = 0; j < 4; j++)
#pragma unroll
                for (int c = 0; c < 4; c++) acc[g][i][j][c] = 0.0f;

    auto issue = [&](int stage, int kc) {
        float* As = sm + stage * STAGE_FLOATS;
        float* Bs = As + BM * SA;
        const float* Ag = A + (size_t)(m0 + am) * K + kc + aq;
        cp16(smem_u32(As + am * SA + aq), Ag);
        cp16(smem_u32(As + (am + 64) * SA + aq), Ag + (size_t)64 * K);
#pragma unroll
        for (int s = 0; s < 6; s++) {
            int id = t + 512 * s;
            int g = id >> 10;
            int n = (id >> 3) & 127;
            int q = (id & 7) * 4;
            cp16(smem_u32(Bs + (g * BN + n) * SA + q),
                 W + (size_t)(g * HH_ + n0 + n) * K + kc + q);
        }
        asm volatile("cp.async.commit_group;\n");
    };

    const int NC = K / BK;   // 64
    issue(0, 0);

    for (int c = 0; c < NC; c++) {
        if (c + 1 < NC) {
            issue((c + 1) & 1, (c + 1) * BK);
            asm volatile("cp.async.wait_group 1;\n");
        } else {
            asm volatile("cp.async.wait_group 0;\n");
        }
        __syncthreads();

        const float* As = sm + (c & 1) * STAGE_FLOATS;
        const float* Bs = As + BM * SA;

#pragma unroll
        for (int kk = 0; kk < BK; kk += 8) {
            float a[2][4];
#pragma unroll
            for (int i = 0; i < 2; i++) {
                const float* p = As + (wm + i * 16 + lr) * SA + kk + lc;
                a[i][0] = p[0];
                a[i][2] = p[4];
                a[i][1] = p[8 * SA];
                a[i][3] = p[8 * SA + 4];
            }
#pragma unroll
            for (int g = 0; g < 3; g++) {
#pragma unroll
                for (int j = 0; j < 4; j++) {
                    const float* p = Bs + (g * BN + wn + j * 8 + lr) * SA + kk + lc;
                    float b0 = p[0], b1 = p[4];
                    mma_tf32(acc[g][0][j], a[0], b0, b1);
                    mma_tf32(acc[g][1][j], a[1], b0, b1);
                }
            }
        }
        __syncthreads();
    }

    // ---------------- Epilogue ----------------
    if (MODE == 0) {
#pragma unroll
        for (int i = 0; i < 2; i++) {
            int m = m0 + wm + i * 16 + lr;
#pragma unroll
            for (int j = 0; j < 4; j++) {
                int n = wn + j * 8 + 2 * lc;
#pragma unroll
                for (int g = 0; g < 3; g++) {
                    int col = g * HH_ + n0 + n;
                    float2 b = *(const float2*)(bias + col);
                    float2 v0 = make_float2(acc[g][i][j][0] + b.x, acc[g][i][j][1] + b.y);
                    float2 v1 = make_float2(acc[g][i][j][2] + b.x, acc[g][i][j][3] + b.y);
                    *(float2*)(out + (size_t)m * K3_ + col) = v0;
                    *(float2*)(out + (size_t)(m + 8) * K3_ + col) = v1;
                }
            }
        }
    } else {
#pragma unroll
        for (int j = 0; j < 4; j++) {
            int ng = n0 + wn + j * 8 + 2 * lc;
            float2 br  = *(const float2*)(bias + ng);
            float2 bz  = *(const float2*)(bias + HH_ + ng);
            float2 bn2 = *(const float2*)(bias + 2 * HH_ + ng);
#pragma unroll
            for (int i = 0; i < 2; i++) {
                int m = m0 + wm + i * 16 + lr;
#pragma unroll
                for (int half = 0; half < 2; half++) {
                    int mm = m + half * 8;
                    int o  = half * 2;
                    const float* gp = gi + (size_t)mm * K3_ + ng;
                    float2 gr = *(const float2*)(gp);
                    float2 gz = *(const float2*)(gp + HH_);
                    float2 gn = *(const float2*)(gp + 2 * HH_);
                    float2 hv = *(const float2*)(A + (size_t)mm * HH_ + ng);

                    float rx = sigf(gr.x + acc[0][i][j][o]     + br.x);
                    float ry = sigf(gr.y + acc[0][i][j][o + 1] + br.y);
                    float zx = sigf(gz.x + acc[1][i][j][o]     + bz.x);
                    float zy = sigf(gz.y + acc[1][i][j][o + 1] + bz.y);
                    float nx = tanhf(gn.x + rx * (acc[2][i][j][o]     + bn2.x));
                    float ny = tanhf(gn.y + ry * (acc[2][i][j][o + 1] + bn2.y));

                    float2 ho = make_float2(nx + zx * (hv.x - nx),
                                            ny + zy * (hv.y - ny));
                    *(float2*)(out + (size_t)mm * HH_ + ng) = ho;
                }
            }
        }
    }
}

// Iteration 0 (h == 0): pure elementwise from gi.
__global__ void iter0_kernel(const float* __restrict__ gi,
                             const float* __restrict__ bhh,
                             float* __restrict__ h)
{
    int idx = blockIdx.x * blockDim.x + threadIdx.x;   // over 8192*2048
    int m = idx >> 11;
    int n = idx & (HH_ - 1);
    const float* gp = gi + (size_t)m * K3_ + n;
    float r = sigf(gp[0] + bhh[n]);
    float z = sigf(gp[HH_] + bhh[HH_ + n]);
    float tv = tanhf(gp[2 * HH_] + r * bhh[2 * HH_ + n]);
    h[idx] = (1.0f - z) * tv;
}

extern "C" void kernel_launch(void* const* d_in, const int* in_sizes, int n_in,
                              void* d_out, int out_size)
{
    const float* enc  = (const float*)d_in[0];
    const float* w_ih = (const float*)d_in[1];
    const float* w_hh = (const float*)d_in[2];
    const float* b_ih = (const float*)d_in[3];
    const float* b_hh = (const float*)d_in[4];
    float* out = (float*)d_out;

    cudaFuncSetAttribute(gru_gemm<0>, cudaFuncAttributeMaxDynamicSharedMemorySize, SMEM_BYTES);
    cudaFuncSetAttribute(gru_gemm<1>, cudaFuncAttributeMaxDynamicSharedMemorySize, SMEM_BYTES);

    float* gi;
    float* hbuf;
    cudaGetSymbolAddress((void**)&gi, g_gi);
    cudaGetSymbolAddress((void**)&hbuf, g_h);
    float* h0 = hbuf;
    float* h1 = hbuf + (size_t)MB_ * HH_;

    dim3 grid(HH_ / BN, MB_ / BM);   // (16, 64)

    // gi = enc @ w_ih^T + b_ih
    gru_gemm<0><<<grid, NTH, SMEM_BYTES>>>(enc, w_ih, b_ih, gi, nullptr);

    // iteration 0 (h=0)
    iter0_kernel<<<(MB_ * HH_) / 256, 256>>>(gi, b_hh, h0);

    // iterations 1..9
    float* hin = h0;
    for (int it = 1; it < NITER; it++) {
        float* ho = (it == NITER - 1) ? out : ((hin == h0) ? h1 : h0);
        gru_gemm<1><<<grid, NTH, SMEM_BYTES>>>(hin, w_hh, b_hh, ho, gi);
        hin = ho;
    }
}

// round 3
// speedup vs baseline: 1.6755x; 1.6755x over previous
#include <cuda_runtime.h>
#include <cuda_fp16.h>
#include <cstdint>

// Problem constants (RecCore: B=8192, D=2048, H=2048, 10 iterations)
#define MB_  8192
#define HH_  2048
#define K3_  (3 * HH_)
#define NITER 10

#define BM 128
#define BN 128                    // per gate; 3 gates stacked
#define BK 64                     // fp16 elems per chunk row = 128 bytes
#define NC 32                     // 2048 / 64
#define NTH 512
#define NSTAGE 3
#define STAGE_BYTES ((BM + 3 * BN) * 128)      // 512 rows * 128B = 65536
#define SMEM_TOTAL (NSTAGE * STAGE_BYTES)      // 196608

// Scratch
__device__ float  g_gi[(long long)MB_ * K3_];
__device__ float  g_hf[2][(long long)MB_ * HH_];
__device__ __half g_h16[2][(long long)MB_ * HH_];
__device__ __half g_w16[(long long)K3_ * HH_];
__device__ __half g_enc16[(long long)MB_ * HH_];

__device__ __forceinline__ uint32_t smem_u32(const void* p) {
    return (uint32_t)__cvta_generic_to_shared(p);
}
__device__ __forceinline__ void cp16(uint32_t s, const void* g) {
    asm volatile("cp.async.cg.shared.global [%0], [%1], 16;\n" :: "r"(s), "l"(g));
}
__device__ __forceinline__ float sigf(float x) {
    return 1.0f / (1.0f + __expf(-x));
}
__device__ __forceinline__ void ldsm4(uint32_t* r, uint32_t addr) {
    asm volatile("ldmatrix.sync.aligned.m8n8.x4.shared.b16 {%0,%1,%2,%3}, [%4];"
                 : "=r"(r[0]), "=r"(r[1]), "=r"(r[2]), "=r"(r[3]) : "r"(addr));
}
__device__ __forceinline__ void mma16816(float* c, const uint32_t* a, uint32_t b0, uint32_t b1) {
    asm volatile(
        "mma.sync.aligned.m16n8k16.row.col.f32.f16.f16.f32 "
        "{%0,%1,%2,%3}, {%4,%5,%6,%7}, {%8,%9}, {%0,%1,%2,%3};\n"
        : "+f"(c[0]), "+f"(c[1]), "+f"(c[2]), "+f"(c[3])
        : "r"(a[0]), "r"(a[1]), "r"(a[2]), "r"(a[3]), "r"(b0), "r"(b1));
}
__device__ __forceinline__ uint32_t swz(uint32_t off) {
    return off ^ ((off >> 3) & 0x70);
}

// Fused 3-gate fp16 GEMM (HMMA m16n8k16 + ldmatrix), fp32 accumulate.
// MODE 0: outf[m, g*H+n] = sum_k A16[m,k]*W16[g*H+n,k] + bias[g*H+n]
// MODE 1: GRU step epilogue; reads gi + hf_in, writes outf (h fp32) + out16 (h fp16)
template <int MODE>
__global__ void __launch_bounds__(NTH, 1)
gru_h(const __half* __restrict__ A16,    // [8192, 2048]
      const __half* __restrict__ W16,    // [6144, 2048]
      const float*  __restrict__ bias,   // [6144]
      const float*  __restrict__ gi,     // MODE 1
      const float*  __restrict__ hf_in,  // MODE 1 (fp32 h matching A16)
      float*        __restrict__ outf,
      __half*       __restrict__ out16)  // MODE 1
{
    extern __shared__ char smc[];
    const uint32_t sbase = smem_u32(smc);
    const int t = threadIdx.x;
    const int wid = t >> 5, lane = t & 31;
    const int m0 = blockIdx.y * BM;
    const int n0 = blockIdx.x * BN;
    const int wm = (wid >> 2) * 32;     // warp m offset (0,32,64,96)
    const int wn = (wid & 3) * 32;      // warp n offset (0,32,64,96)
    const int lr = lane >> 2;           // 0..7
    const int lc = lane & 3;            // 0..3

    float acc[3][2][4][4];
#pragma unroll
    for (int g = 0; g < 3; g++)
#pragma unroll
        for (int i = 0; i < 2; i++)
#pragma unroll
            for (int j = 0; j < 4; j++)
#pragma unroll
                for (int c = 0; c < 4; c++) acc[g][i][j][c] = 0.0f;

    // loader: 512 rows x 128B per stage; 8 x 16B per thread
    auto issue = [&](int stage, int kc) {   // kc in fp16 elems
        uint32_t st = sbase + stage * STAGE_BYTES;
#pragma unroll
        for (int i = 0; i < 8; i++) {
            int id = t + NTH * i;          // 0..4095
            int row = id >> 3;             // 0..511
            int qb = (id & 7) * 16;        // byte offset in row
            const __half* gsrc;
            if (row < BM) {
                gsrc = A16 + (size_t)(m0 + row) * HH_ + kc + (qb >> 1);
            } else {
                int r = row - BM;
                int g = r >> 7, n = r & 127;
                gsrc = W16 + ((size_t)g * HH_ + n0 + n) * HH_ + kc + (qb >> 1);
            }
            cp16(st + swz(row * 128 + qb), gsrc);
        }
        asm volatile("cp.async.commit_group;\n" ::: "memory");
    };

    issue(0, 0);
    issue(1, BK);

    // ldmatrix lane addressing (byte offsets within stage)
    const int a_row = lane & 15;               // A: rows m (x4: [m0-7 k0][m8-15 k0][m0-7 k8][m8-15 k8])
    const int a_kb  = (lane >> 4) * 16;
    const int b_row = (lane & 7) | ((lane & 16) >> 1);   // B: n rows
    const int b_kb  = (lane & 8) * 2;

    for (int c = 0; c < NC; c++) {
        if (c < NC - 1) asm volatile("cp.async.wait_group 1;\n" ::: "memory");
        else            asm volatile("cp.async.wait_group 0;\n" ::: "memory");
        __syncthreads();
        if (c + 2 < NC) issue((c + 2) % NSTAGE, (c + 2) * BK);

        uint32_t st = sbase + (c % NSTAGE) * STAGE_BYTES;
#pragma unroll
        for (int s = 0; s < 4; s++) {          // k16 steps within chunk
            uint32_t a[2][4];
#pragma unroll
            for (int i = 0; i < 2; i++) {
                uint32_t off = (uint32_t)(wm + i * 16 + a_row) * 128 + s * 32 + a_kb;
                ldsm4(a[i], st + swz(off));
            }
#pragma unroll
            for (int g = 0; g < 3; g++) {
#pragma unroll
                for (int j2 = 0; j2 < 2; j2++) {
                    uint32_t off = (uint32_t)(BM + g * BN + wn + j2 * 16 + b_row) * 128
                                   + s * 32 + b_kb;
                    uint32_t b[4];
                    ldsm4(b, st + swz(off));
#pragma unroll
                    for (int i = 0; i < 2; i++) {
                        mma16816(acc[g][i][2 * j2],     a[i], b[0], b[1]);
                        mma16816(acc[g][i][2 * j2 + 1], a[i], b[2], b[3]);
                    }
                }
            }
        }
    }

    // ---------------- Epilogue ----------------
    if (MODE == 0) {
#pragma unroll
        for (int i = 0; i < 2; i++) {
            int m = m0 + wm + i * 16 + lr;
#pragma unroll
            for (int j = 0; j < 4; j++) {
                int n = wn + j * 8 + 2 * lc;
#pragma unroll
                for (int g = 0; g < 3; g++) {
                    int col = g * HH_ + n0 + n;
                    float2 b = *(const float2*)(bias + col);
                    float2 v0 = make_float2(acc[g][i][j][0] + b.x, acc[g][i][j][1] + b.y);
                    float2 v1 = make_float2(acc[g][i][j][2] + b.x, acc[g][i][j][3] + b.y);
                    *(float2*)(outf + (size_t)m * K3_ + col) = v0;
                    *(float2*)(outf + (size_t)(m + 8) * K3_ + col) = v1;
                }
            }
        }
    } else {
#pragma unroll
        for (int j = 0; j < 4; j++) {
            int ng = n0 + wn + j * 8 + 2 * lc;
            float2 br  = *(const float2*)(bias + ng);
            float2 bz  = *(const float2*)(bias + HH_ + ng);
            float2 bn2 = *(const float2*)(bias + 2 * HH_ + ng);
#pragma unroll
            for (int i = 0; i < 2; i++) {
                int m = m0 + wm + i * 16 + lr;
#pragma unroll
                for (int half = 0; half < 2; half++) {
                    int mm = m + half * 8;
                    int o  = half * 2;
                    const float* gp = gi + (size_t)mm * K3_ + ng;
                    float2 gr = *(const float2*)(gp);
                    float2 gz = *(const float2*)(gp + HH_);
                    float2 gn = *(const float2*)(gp + 2 * HH_);
                    float2 hv = *(const float2*)(hf_in + (size_t)mm * HH_ + ng);

                    float rx = sigf(gr.x + acc[0][i][j][o]     + br.x);
                    float ry = sigf(gr.y + acc[0][i][j][o + 1] + br.y);
                    float zx = sigf(gz.x + acc[1][i][j][o]     + bz.x);
                    float zy = sigf(gz.y + acc[1][i][j][o + 1] + bz.y);
                    float nx = tanhf(gn.x + rx * (acc[2][i][j][o]     + bn2.x));
                    float ny = tanhf(gn.y + ry * (acc[2][i][j][o + 1] + bn2.y));

                    float2 ho = make_float2(nx + zx * (hv.x - nx),
                                            ny + zy * (hv.y - ny));
                    *(float2*)(outf + (size_t)mm * HH_ + ng) = ho;
                    *(__half2*)(out16 + (size_t)mm * HH_ + ng) = __floats2half2_rn(ho.x, ho.y);
                }
            }
        }
    }
}

// float -> half conversion (vectorized)
__global__ void f2h_kernel(const float* __restrict__ src, __half* __restrict__ dst, int n4)
{
    int i = blockIdx.x * blockDim.x + threadIdx.x;
    if (i < n4) {
        float4 v = ((const float4*)src)[i];
        __half2 lo = __floats2half2_rn(v.x, v.y);
        __half2 hi = __floats2half2_rn(v.z, v.w);
        ((__half2*)dst)[2 * i]     = lo;
        ((__half2*)dst)[2 * i + 1] = hi;
    }
}

// Iteration 0 (h == 0): elementwise from gi; writes fp32 + fp16 h
__global__ void iter0_kernel(const float* __restrict__ gi,
                             const float* __restrict__ bhh,
                             float* __restrict__ hf,
                             __half* __restrict__ h16)
{
    int idx = blockIdx.x * blockDim.x + threadIdx.x;
    int m = idx >> 11;
    int n = idx & (HH_ - 1);
    const float* gp = gi + (size_t)m * K3_ + n;
    float r = sigf(gp[0] + bhh[n]);
    float z = sigf(gp[HH_] + bhh[HH_ + n]);
    float tv = tanhf(gp[2 * HH_] + r * bhh[2 * HH_ + n]);
    float h = (1.0f - z) * tv;
    hf[idx] = h;
    h16[idx] = __float2half_rn(h);
}

extern "C" void kernel_launch(void* const* d_in, const int* in_sizes, int n_in,
                              void* d_out, int out_size)
{
    const float* enc  = (const float*)d_in[0];
    const float* w_ih = (const float*)d_in[1];
    const float* w_hh = (const float*)d_in[2];
    const float* b_ih = (const float*)d_in[3];
    const float* b_hh = (const float*)d_in[4];
    float* out = (float*)d_out;

    cudaFuncSetAttribute(gru_h<0>, cudaFuncAttributeMaxDynamicSharedMemorySize, SMEM_TOTAL);
    cudaFuncSetAttribute(gru_h<1>, cudaFuncAttributeMaxDynamicSharedMemorySize, SMEM_TOTAL);

    float *gi, *hf;
    __half *h16, *w16, *e16;
    cudaGetSymbolAddress((void**)&gi,  g_gi);
    cudaGetSymbolAddress((void**)&hf,  g_hf);
    cudaGetSymbolAddress((void**)&h16, g_h16);
    cudaGetSymbolAddress((void**)&w16, g_w16);
    cudaGetSymbolAddress((void**)&e16, g_enc16);
    const size_t HN = (size_t)MB_ * HH_;

    dim3 grid(HH_ / BN, MB_ / BM);   // (16, 64)

    // convert enc + w_ih
    f2h_kernel<<<(MB_ * HH_ / 4 + 255) / 256, 256>>>(enc, e16, MB_ * HH_ / 4);
    f2h_kernel<<<(K3_ * HH_ / 4 + 255) / 256, 256>>>(w_ih, w16, K3_ * HH_ / 4);

    // gi = enc @ w_ih^T + b_ih
    gru_h<0><<<grid, NTH, SMEM_TOTAL>>>(e16, w16, b_ih, nullptr, nullptr, gi, nullptr);

    // iteration 0 (h = 0)
    iter0_kernel<<<(MB_ * HH_) / 256, 256>>>(gi, b_hh, hf, h16);

    // convert w_hh (stream-ordered after GEMM0 consumed w_ih16)
    f2h_kernel<<<(K3_ * HH_ / 4 + 255) / 256, 256>>>(w_hh, w16, K3_ * HH_ / 4);

    // iterations 1..9
    int p = 0;
    for (int it = 1; it < NITER; it++) {
        float*  hfo  = (it == NITER - 1) ? out : (hf + (1 - p) * HN);
        __half* h16o = h16 + (1 - p) * HN;
        gru_h<1><<<grid, NTH, SMEM_TOTAL>>>(h16 + p * HN, w16, b_hh,
                                            gi, hf + p * HN, hfo, h16o);
        p = 1 - p;
    }
}

// round 7
// speedup vs baseline: 1.8368x; 1.0963x over previous
#include <cuda_runtime.h>
#include <cuda_fp16.h>
#include <cstdint>

// Problem constants (RecCore: B=8192, D=2048, H=2048, 10 iterations)
#define MB_  8192
#define HH_  2048
#define K3_  (3 * HH_)
#define NITER 10

#define BM 128
#define BN 128                    // per gate; 3 gates stacked
#define BK 64                     // fp16 elems per chunk row = 128 bytes
#define NC 32                     // 2048 / 64
#define NTH 512
#define NSTAGE 3
#define STAGE_BYTES ((BM + 3 * BN) * 128)      // 512 rows * 128B = 65536
#define SMEM_TOTAL (NSTAGE * STAGE_BYTES)      // 196608

// Scratch
__device__ float  g_gi[(long long)MB_ * K3_];
__device__ __half g_h16[2][(long long)MB_ * HH_];
__device__ __half g_w16[(long long)K3_ * HH_];
__device__ __half g_enc16[(long long)MB_ * HH_];

__device__ __forceinline__ uint32_t smem_u32(const void* p) {
    return (uint32_t)__cvta_generic_to_shared(p);
}
__device__ __forceinline__ void cp16(uint32_t s, const void* g) {
    asm volatile("cp.async.cg.shared.global [%0], [%1], 16;\n" :: "r"(s), "l"(g));
}
__device__ __forceinline__ float sigf(float x) {
    return 1.0f / (1.0f + __expf(-x));
}
__device__ __forceinline__ void ldsm4(uint32_t* r, uint32_t addr) {
    asm volatile("ldmatrix.sync.aligned.m8n8.x4.shared.b16 {%0,%1,%2,%3}, [%4];"
                 : "=r"(r[0]), "=r"(r[1]), "=r"(r[2]), "=r"(r[3]) : "r"(addr));
}
__device__ __forceinline__ void mma16816(float* c, const uint32_t* a, uint32_t b0, uint32_t b1) {
    asm volatile(
        "mma.sync.aligned.m16n8k16.row.col.f32.f16.f16.f32 "
        "{%0,%1,%2,%3}, {%4,%5,%6,%7}, {%8,%9}, {%0,%1,%2,%3};\n"
        : "+f"(c[0]), "+f"(c[1]), "+f"(c[2]), "+f"(c[3])
        : "r"(a[0]), "r"(a[1]), "r"(a[2]), "r"(a[3]), "r"(b0), "r"(b1));
}
__device__ __forceinline__ uint32_t swz(uint32_t off) {
    return off ^ ((off >> 3) & 0x70);
}

// Fused 3-gate fp16 GEMM (HMMA m16n8k16 + ldmatrix), fp32 accumulate.
// MODE 0: outf[m, g*H+n] = sum_k A16[m,k]*W16[g*H+n,k] + bias[g*H+n]   (gi precompute)
// MODE 1: GRU step, intermediate: write h16 only
// MODE 2: GRU step, final: write fp32 out only
template <int MODE>
__global__ void __launch_bounds__(NTH, 1)
gru_h(const __half* __restrict__ A16,    // [8192, 2048]  (enc16 or h16_in)
      const __half* __restrict__ W16,    // [6144, 2048]
      const float*  __restrict__ bias,   // [6144]
      const float*  __restrict__ gi,     // MODE 1/2
      float*        __restrict__ outf,   // MODE 0 (gi) or MODE 2 (h out fp32)
      __half*       __restrict__ out16)  // MODE 1 (h out fp16)
{
    extern __shared__ char smc[];
    const uint32_t sbase = smem_u32(smc);
    const int t = threadIdx.x;
    const int wid = t >> 5, lane = t & 31;
    const int m0 = blockIdx.y * BM;
    const int n0 = blockIdx.x * BN;
    const int wm = (wid >> 2) * 32;     // warp m offset
    const int wn = (wid & 3) * 32;      // warp n offset
    const int lr = lane >> 2;           // 0..7
    const int lc = lane & 3;            // 0..3

    float acc[3][2][4][4];
#pragma unroll
    for (int g = 0; g < 3; g++)
#pragma unroll
        for (int i = 0; i < 2; i++)
#pragma unroll
            for (int j = 0; j < 4; j++)
#pragma unroll
                for (int c = 0; c < 4; c++) acc[g][i][j][c] = 0.0f;

    // loader: 512 rows x 128B per stage; 8 x 16B per thread
    auto issue = [&](int stage, int kc) {   // kc in fp16 elems
        uint32_t st = sbase + stage * STAGE_BYTES;
#pragma unroll
        for (int i = 0; i < 8; i++) {
            int id = t + NTH * i;          // 0..4095
            int row = id >> 3;             // 0..511
            int qb = (id & 7) * 16;        // byte offset in row
            const __half* gsrc;
            if (row < BM) {
                gsrc = A16 + (size_t)(m0 + row) * HH_ + kc + (qb >> 1);
            } else {
                int r = row - BM;
                int g = r >> 7, n = r & 127;
                gsrc = W16 + ((size_t)g * HH_ + n0 + n) * HH_ + kc + (qb >> 1);
            }
            cp16(st + swz(row * 128 + qb), gsrc);
        }
        asm volatile("cp.async.commit_group;\n" ::: "memory");
    };

    issue(0, 0);
    issue(1, BK);

    // ldmatrix lane addressing
    const int a_row = lane & 15;
    const int a_kb  = (lane >> 4) * 16;
    const int b_row = (lane & 7) | ((lane & 16) >> 1);
    const int b_kb  = (lane & 8) * 2;

    for (int c = 0; c < NC; c++) {
        if (c < NC - 1) asm volatile("cp.async.wait_group 1;\n" ::: "memory");
        else            asm volatile("cp.async.wait_group 0;\n" ::: "memory");
        __syncthreads();
        if (c + 2 < NC) issue((c + 2) % NSTAGE, (c + 2) * BK);

        uint32_t st = sbase + (c % NSTAGE) * STAGE_BYTES;
#pragma unroll
        for (int s = 0; s < 4; s++) {          // k16 steps within chunk
            uint32_t a[2][4];
#pragma unroll
            for (int i = 0; i < 2; i++) {
                uint32_t off = (uint32_t)(wm + i * 16 + a_row) * 128 + s * 32 + a_kb;
                ldsm4(a[i], st + swz(off));
            }
            // B double-buffered software pipeline over 6 fragment groups
            uint32_t b[2][4];
            auto baddr = [&](int nx) {        // nx = g*2 + j2
                int g = nx >> 1, j2 = nx & 1;
                uint32_t off = (uint32_t)(BM + g * BN + wn + j2 * 16 + b_row) * 128
                               + s * 32 + b_kb;
                return st + swz(off);
            };
            ldsm4(b[0], baddr(0));
#pragma unroll
            for (int nx = 0; nx < 6; nx++) {
                int bi = nx & 1;
                if (nx < 5) ldsm4(b[bi ^ 1], baddr(nx + 1));
                int g = nx >> 1, j2 = nx & 1;
                mma16816(acc[g][0][2 * j2],     a[0], b[bi][0], b[bi][1]);
                mma16816(acc[g][0][2 * j2 + 1], a[0], b[bi][2], b[bi][3]);
                mma16816(acc[g][1][2 * j2],     a[1], b[bi][0], b[bi][1]);
                mma16816(acc[g][1][2 * j2 + 1], a[1], b[bi][2], b[bi][3]);
            }
        }
    }

    // ---------------- Epilogue ----------------
    if (MODE == 0) {
#pragma unroll
        for (int i = 0; i < 2; i++) {
            int m = m0 + wm + i * 16 + lr;
#pragma unroll
            for (int j = 0; j < 4; j++) {
                int n = wn + j * 8 + 2 * lc;
#pragma unroll
                for (int g = 0; g < 3; g++) {
                    int col = g * HH_ + n0 + n;
                    float2 b = *(const float2*)(bias + col);
                    float2 v0 = make_float2(acc[g][i][j][0] + b.x, acc[g][i][j][1] + b.y);
                    float2 v1 = make_float2(acc[g][i][j][2] + b.x, acc[g][i][j][3] + b.y);
                    *(float2*)(outf + (size_t)m * K3_ + col) = v0;
                    *(float2*)(outf + (size_t)(m + 8) * K3_ + col) = v1;
                }
            }
        }
    } else {
#pragma unroll
        for (int j = 0; j < 4; j++) {
            int ng = n0 + wn + j * 8 + 2 * lc;
            float2 br  = *(const float2*)(bias + ng);
            float2 bz  = *(const float2*)(bias + HH_ + ng);
            float2 bn2 = *(const float2*)(bias + 2 * HH_ + ng);
#pragma unroll
            for (int i = 0; i < 2; i++) {
                int m = m0 + wm + i * 16 + lr;
#pragma unroll
                for (int half = 0; half < 2; half++) {
                    int mm = m + half * 8;
                    int o  = half * 2;
                    const float* gp = gi + (size_t)mm * K3_ + ng;
                    float2 gr = *(const float2*)(gp);
                    float2 gz = *(const float2*)(gp + HH_);
                    float2 gn = *(const float2*)(gp + 2 * HH_);
                    __half2 h2 = *(const __half2*)(A16 + (size_t)mm * HH_ + ng);
                    float2 hv = __half22float2(h2);

                    float rx = sigf(gr.x + acc[0][i][j][o]     + br.x);
                    float ry = sigf(gr.y + acc[0][i][j][o + 1] + br.y);
                    float zx = sigf(gz.x + acc[1][i][j][o]     + bz.x);
                    float zy = sigf(gz.y + acc[1][i][j][o + 1] + bz.y);
                    float nx = tanhf(gn.x + rx * (acc[2][i][j][o]     + bn2.x));
                    float ny = tanhf(gn.y + ry * (acc[2][i][j][o + 1] + bn2.y));

                    float hx = nx + zx * (hv.x - nx);
                    float hy = ny + zy * (hv.y - ny);

                    if (MODE == 1) {
                        *(__half2*)(out16 + (size_t)mm * HH_ + ng) = __floats2half2_rn(hx, hy);
                    } else {
                        *(float2*)(outf + (size_t)mm * HH_ + ng) = make_float2(hx, hy);
                    }
                }
            }
        }
    }
}

// float -> half conversion (vectorized)
__global__ void f2h_kernel(const float* __restrict__ src, __half* __restrict__ dst, int n4)
{
    int i = blockIdx.x * blockDim.x + threadIdx.x;
    if (i < n4) {
        float4 v = ((const float4*)src)[i];
        ((__half2*)dst)[2 * i]     = __floats2half2_rn(v.x, v.y);
        ((__half2*)dst)[2 * i + 1] = __floats2half2_rn(v.z, v.w);
    }
}

// Iteration 0 (h == 0): elementwise from gi; writes fp16 h only. float4-vectorized.
__global__ void iter0_kernel(const float* __restrict__ gi,
                             const float* __restrict__ bhh,
                             __half* __restrict__ h16)
{
    int idx = blockIdx.x * blockDim.x + threadIdx.x;   // over MB_*HH_/4
    int m = idx >> 9;
    int n = (idx & 511) * 4;
    const float* gp = gi + (size_t)m * K3_ + n;
    float4 a = *(const float4*)(gp);
    float4 b = *(const float4*)(gp + HH_);
    float4 c = *(const float4*)(gp + 2 * HH_);
    float4 v1 = *(const float4*)(bhh + n);
    float4 v2 = *(const float4*)(bhh + HH_ + n);
    float4 v3 = *(const float4*)(bhh + 2 * HH_ + n);
    float h[4];
    {
        float r = sigf(a.x + v1.x), z = sigf(b.x + v2.x);
        h[0] = (1.0f - z) * tanhf(c.x + r * v3.x);
    }
    {
        float r = sigf(a.y + v1.y), z = sigf(b.y + v2.y);
        h[1] = (1.0f - z) * tanhf(c.y + r * v3.y);
    }
    {
        float r = sigf(a.z + v1.z), z = sigf(b.z + v2.z);
        h[2] = (1.0f - z) * tanhf(c.z + r * v3.z);
    }
    {
        float r = sigf(a.w + v1.w), z = sigf(b.w + v2.w);
        h[3] = (1.0f - z) * tanhf(c.w + r * v3.w);
    }
    __half2* dst = (__half2*)(h16 + (size_t)m * HH_ + n);
    dst[0] = __floats2half2_rn(h[0], h[1]);
    dst[1] = __floats2half2_rn(h[2], h[3]);
}

extern "C" void kernel_launch(void* const* d_in, const int* in_sizes, int n_in,
                              void* d_out, int out_size)
{
    const float* enc  = (const float*)d_in[0];
    const float* w_ih = (const float*)d_in[1];
    const float* w_hh = (const float*)d_in[2];
    const float* b_ih = (const float*)d_in[3];
    const float* b_hh = (const float*)d_in[4];
    float* out = (float*)d_out;

    cudaFuncSetAttribute(gru_h<0>, cudaFuncAttributeMaxDynamicSharedMemorySize, SMEM_TOTAL);
    cudaFuncSetAttribute(gru_h<1>, cudaFuncAttributeMaxDynamicSharedMemorySize, SMEM_TOTAL);
    cudaFuncSetAttribute(gru_h<2>, cudaFuncAttributeMaxDynamicSharedMemorySize, SMEM_TOTAL);

    float *gi;
    __half *h16, *w16, *e16;
    cudaGetSymbolAddress((void**)&gi,  g_gi);
    cudaGetSymbolAddress((void**)&h16, g_h16);
    cudaGetSymbolAddress((void**)&w16, g_w16);
    cudaGetSymbolAddress((void**)&e16, g_enc16);
    const size_t HN = (size_t)MB_ * HH_;

    dim3 grid(HH_ / BN, MB_ / BM);   // (16, 64)

    // convert enc + w_ih
    f2h_kernel<<<(MB_ * HH_ / 4 + 255) / 256, 256>>>(enc, e16, MB_ * HH_ / 4);
    f2h_kernel<<<(K3_ * HH_ / 4 + 255) / 256, 256>>>(w_ih, w16, K3_ * HH_ / 4);

    // gi = enc @ w_ih^T + b_ih
    gru_h<0><<<grid, NTH, SMEM_TOTAL>>>(e16, w16, b_ih, nullptr, gi, nullptr);

    // iteration 0 (h = 0)
    iter0_kernel<<<(MB_ * HH_ / 4) / 256, 256>>>(gi, b_hh, h16);

    // convert w_hh (stream-ordered after GEMM0 consumed w_ih16)
    f2h_kernel<<<(K3_ * HH_ / 4 + 255) / 256, 256>>>(w_hh, w16, K3_ * HH_ / 4);

    // iterations 1..8 (write h16), iteration 9 (write fp32 out)
    int p = 0;
    for (int it = 1; it < NITER - 1; it++) {
        gru_h<1><<<grid, NTH, SMEM_TOTAL>>>(h16 + p * HN, w16, b_hh, gi,
                                            nullptr, h16 + (1 - p) * HN);
        p = 1 - p;
    }
    gru_h<2><<<grid, NTH, SMEM_TOTAL>>>(h16 + p * HN, w16, b_hh, gi, out, nullptr);
}

// round 8
// speedup vs baseline: 2.2738x; 1.2379x over previous
#include <cuda_runtime.h>
#include <cuda_fp16.h>
#include <cstdint>

// Problem constants (RecCore: B=8192, D=2048, H=2048, 10 iterations)
#define MB_  8192
#define HH_  2048
#define K3_  (3 * HH_)
#define NITER 10

#define BM 128
#define BNG 64                    // per-gate N tile
#define NSTK 192                  // stacked B rows (3 gates * 64)
#define BK 64                     // fp16 elems per chunk row = 128 bytes
#define NC 32                     // 2048 / 64
#define NTH 256
#define STAGE_BYTES ((BM + NSTK) * 128)   // 40960
#define SMEM_TOTAL (2 * STAGE_BYTES)      // 81920 -> 2 CTAs/SM

// Scratch
__device__ __half g_gi16[(long long)MB_ * K3_];
__device__ __half g_h16[2][(long long)MB_ * HH_];
__device__ __half g_w16[(long long)K3_ * HH_];
__device__ __half g_e16[(long long)MB_ * HH_];

__device__ __forceinline__ uint32_t smem_u32(const void* p) {
    return (uint32_t)__cvta_generic_to_shared(p);
}
__device__ __forceinline__ void cp16(uint32_t s, const void* g) {
    asm volatile("cp.async.cg.shared.global [%0], [%1], 16;\n" :: "r"(s), "l"(g));
}
__device__ __forceinline__ float tanha(float x) {
    float y;
    asm("tanh.approx.f32 %0, %1;" : "=f"(y) : "f"(x));
    return y;
}
__device__ __forceinline__ float sigf(float x) {
    return 0.5f + 0.5f * tanha(0.5f * x);
}
__device__ __forceinline__ void ldsm4(uint32_t* r, uint32_t addr) {
    asm volatile("ldmatrix.sync.aligned.m8n8.x4.shared.b16 {%0,%1,%2,%3}, [%4];"
                 : "=r"(r[0]), "=r"(r[1]), "=r"(r[2]), "=r"(r[3]) : "r"(addr));
}
__device__ __forceinline__ void mma16816(float* c, const uint32_t* a, uint32_t b0, uint32_t b1) {
    asm volatile(
        "mma.sync.aligned.m16n8k16.row.col.f32.f16.f16.f32 "
        "{%0,%1,%2,%3}, {%4,%5,%6,%7}, {%8,%9}, {%0,%1,%2,%3};\n"
        : "+f"(c[0]), "+f"(c[1]), "+f"(c[2]), "+f"(c[3])
        : "r"(a[0]), "r"(a[1]), "r"(a[2]), "r"(a[3]), "r"(b0), "r"(b1));
}
__device__ __forceinline__ uint32_t swz(uint32_t off) {
    return off ^ ((off >> 3) & 0x70);
}

// Fused 3-gate fp16 GEMM (HMMA m16n8k16 + ldmatrix), fp32 accumulate.
// 256 threads, 2 CTAs/SM. Tile: M=128 x (64 per gate).
// MODE 0: gi16[m, g*H+n] = acc + b_ih  AND  h16 out = GRU step with h=0 (fused iter0)
// MODE 1: GRU step, intermediate: write h16 only
// MODE 2: GRU step, final: write fp32 out only
template <int MODE>
__global__ void __launch_bounds__(NTH, 2)
gru_h(const __half* __restrict__ A16,    // [8192, 2048]  (e16 or h16_in)
      const __half* __restrict__ W16,    // [6144, 2048]
      const float*  __restrict__ b_ih,   // [6144]  (MODE 0)
      const float*  __restrict__ b_hh,   // [6144]
      __half*       __restrict__ gi16,   // written MODE 0, read MODE 1/2
      float*        __restrict__ outf,   // MODE 2
      __half*       __restrict__ out16)  // MODE 0/1
{
    extern __shared__ char smc[];
    const uint32_t sbase = smem_u32(smc);
    const int t = threadIdx.x;
    const int wid = t >> 5, lane = t & 31;
    const int m0 = blockIdx.y * BM;
    const int n0 = blockIdx.x * BNG;
    const int wm  = (wid >> 1) * 32;     // warp m offset (0,32,64,96)
    const int wn2 = (wid & 1) * 32;      // warp n offset within gate (0,32)
    const int lr = lane >> 2;            // 0..7
    const int lc = lane & 3;             // 0..3

    float acc[3][2][2][4];
#pragma unroll
    for (int g = 0; g < 3; g++)
#pragma unroll
        for (int i = 0; i < 2; i++)
#pragma unroll
            for (int j = 0; j < 2; j++)
#pragma unroll
                for (int c = 0; c < 4; c++) acc[g][i][j][c] = 0.0f;
    // NOTE: acc[g][i][j2][c] with j2 over two n8-pairs per 16-row ldsm group; we
    // need 4 n8 frags per gate -> acc2 layout: [g][i][4][4] packed as [g][i][2][4]x2?
    // Use full [3][2][4][4] instead:
    float acc2[3][2][4][4];
#pragma unroll
    for (int g = 0; g < 3; g++)
#pragma unroll
        for (int i = 0; i < 2; i++)
#pragma unroll
            for (int j = 0; j < 4; j++)
#pragma unroll
                for (int c = 0; c < 4; c++) acc2[g][i][j][c] = 0.0f;

    // loader: 320 rows (A:0-127, W stacked:128-319) x 128B; 10 x 16B per thread
    auto issue = [&](int stage, int kc) {   // kc in fp16 elems
        uint32_t st = sbase + stage * STAGE_BYTES;
#pragma unroll
        for (int i = 0; i < 10; i++) {
            int id = t + NTH * i;          // 0..2559
            int row = id >> 3;             // 0..319
            int qb = (id & 7) * 16;        // byte offset in row
            const __half* gsrc;
            if (row < BM) {
                gsrc = A16 + (size_t)(m0 + row) * HH_ + kc + (qb >> 1);
            } else {
                int r = row - BM;
                int g = r >> 6, n = r & 63;
                gsrc = W16 + ((size_t)g * HH_ + n0 + n) * HH_ + kc + (qb >> 1);
            }
            cp16(st + swz(row * 128 + qb), gsrc);
        }
        asm volatile("cp.async.commit_group;\n" ::: "memory");
    };

    issue(0, 0);

    // ldmatrix lane addressing
    const int a_row = lane & 15;
    const int a_kb  = (lane >> 4) * 16;
    const int b_row = (lane & 7) | ((lane & 16) >> 1);
    const int b_kb  = (lane & 8) * 2;

    for (int c = 0; c < NC; c++) {
        asm volatile("cp.async.wait_group 0;\n" ::: "memory");
        __syncthreads();
        if (c + 1 < NC) issue((c + 1) & 1, (c + 1) * BK);

        uint32_t st = sbase + (c & 1) * STAGE_BYTES;
#pragma unroll
        for (int s = 0; s < 4; s++) {          // k16 steps within chunk
            uint32_t a[2][4];
#pragma unroll
            for (int i = 0; i < 2; i++) {
                uint32_t off = (uint32_t)(wm + i * 16 + a_row) * 128 + s * 32 + a_kb;
                ldsm4(a[i], st + swz(off));
            }
            // B double-buffered over 6 fragment groups: nx = g*2 + j2 (16 n-rows each)
            uint32_t b[2][4];
            auto baddr = [&](int nx) {
                int g = nx >> 1, j2 = nx & 1;
                uint32_t off = (uint32_t)(BM + g * BNG + wn2 + j2 * 16 + b_row) * 128
                               + s * 32 + b_kb;
                return st + swz(off);
            };
            ldsm4(b[0], baddr(0));
#pragma unroll
            for (int nx = 0; nx < 6; nx++) {
                int bi = nx & 1;
                if (nx < 5) ldsm4(b[bi ^ 1], baddr(nx + 1));
                int g = nx >> 1, j2 = nx & 1;
                mma16816(acc2[g][0][2 * j2],     a[0], b[bi][0], b[bi][1]);
                mma16816(acc2[g][0][2 * j2 + 1], a[0], b[bi][2], b[bi][3]);
                mma16816(acc2[g][1][2 * j2],     a[1], b[bi][0], b[bi][1]);
                mma16816(acc2[g][1][2 * j2 + 1], a[1], b[bi][2], b[bi][3]);
            }
        }
    }

    // ---------------- Epilogue ----------------
#pragma unroll
    for (int j = 0; j < 4; j++) {
        int ngl = n0 + wn2 + j * 8 + 2 * lc;     // global per-gate col (even)
        float2 bhr = *(const float2*)(b_hh + ngl);
        float2 bhz = *(const float2*)(b_hh + HH_ + ngl);
        float2 bhn = *(const float2*)(b_hh + 2 * HH_ + ngl);
        float2 bir, biz, bin;
        if (MODE == 0) {
            bir = *(const float2*)(b_ih + ngl);
            biz = *(const float2*)(b_ih + HH_ + ngl);
            bin = *(const float2*)(b_ih + 2 * HH_ + ngl);
        }
#pragma unroll
        for (int i = 0; i < 2; i++) {
            int m = m0 + wm + i * 16 + lr;
#pragma unroll
            for (int half = 0; half < 2; half++) {
                int mm = m + half * 8;
                int o  = half * 2;

                if (MODE == 0) {
                    float grx = acc2[0][i][j][o]     + bir.x;
                    float gry = acc2[0][i][j][o + 1] + bir.y;
                    float gzx = acc2[1][i][j][o]     + biz.x;
                    float gzy = acc2[1][i][j][o + 1] + biz.y;
                    float gnx = acc2[2][i][j][o]     + bin.x;
                    float gny = acc2[2][i][j][o + 1] + bin.y;
                    __half* gp = gi16 + (size_t)mm * K3_ + ngl;
                    *(__half2*)(gp)            = __floats2half2_rn(grx, gry);
                    *(__half2*)(gp + HH_)      = __floats2half2_rn(gzx, gzy);
                    *(__half2*)(gp + 2 * HH_)  = __floats2half2_rn(gnx, gny);
                    // fused iteration 0 (h = 0)
                    float rx = sigf(grx + bhr.x), ry = sigf(gry + bhr.y);
                    float zx = sigf(gzx + bhz.x), zy = sigf(gzy + bhz.y);
                    float nx = tanha(gnx + rx * bhn.x);
                    float ny = tanha(gny + ry * bhn.y);
                    float hx = (1.0f - zx) * nx;
                    float hy = (1.0f - zy) * ny;
                    *(__half2*)(out16 + (size_t)mm * HH_ + ngl) = __floats2half2_rn(hx, hy);
                } else {
                    const __half* gp = gi16 + (size_t)mm * K3_ + ngl;
                    float2 gr = __half22float2(*(const __half2*)(gp));
                    float2 gz = __half22float2(*(const __half2*)(gp + HH_));
                    float2 gn = __half22float2(*(const __half2*)(gp + 2 * HH_));
                    float2 hv = __half22float2(*(const __half2*)(A16 + (size_t)mm * HH_ + ngl));

                    float rx = sigf(gr.x + acc2[0][i][j][o]     + bhr.x);
                    float ry = sigf(gr.y + acc2[0][i][j][o + 1] + bhr.y);
                    float zx = sigf(gz.x + acc2[1][i][j][o]     + bhz.x);
                    float zy = sigf(gz.y + acc2[1][i][j][o + 1] + bhz.y);
                    float nx = tanha(gn.x + rx * (acc2[2][i][j][o]     + bhn.x));
                    float ny = tanha(gn.y + ry * (acc2[2][i][j][o + 1] + bhn.y));

                    float hx = nx + zx * (hv.x - nx);
                    float hy = ny + zy * (hv.y - ny);

                    if (MODE == 1) {
                        *(__half2*)(out16 + (size_t)mm * HH_ + ngl) = __floats2half2_rn(hx, hy);
                    } else {
                        *(float2*)(outf + (size_t)mm * HH_ + ngl) = make_float2(hx, hy);
                    }
                }
            }
        }
    }
}

// float -> half conversion (vectorized)
__global__ void f2h_kernel(const float* __restrict__ src, __half* __restrict__ dst, int n4)
{
    int i = blockIdx.x * blockDim.x + threadIdx.x;
    if (i < n4) {
        float4 v = ((const float4*)src)[i];
        ((__half2*)dst)[2 * i]     = __floats2half2_rn(v.x, v.y);
        ((__half2*)dst)[2 * i + 1] = __floats2half2_rn(v.z, v.w);
    }
}

extern "C" void kernel_launch(void* const* d_in, const int* in_sizes, int n_in,
                              void* d_out, int out_size)
{
    const float* enc  = (const float*)d_in[0];
    const float* w_ih = (const float*)d_in[1];
    const float* w_hh = (const float*)d_in[2];
    const float* b_ih = (const float*)d_in[3];
    const float* b_hh = (const float*)d_in[4];
    float* out = (float*)d_out;

    cudaFuncSetAttribute(gru_h<0>, cudaFuncAttributeMaxDynamicSharedMemorySize, SMEM_TOTAL);
    cudaFuncSetAttribute(gru_h<1>, cudaFuncAttributeMaxDynamicSharedMemorySize, SMEM_TOTAL);
    cudaFuncSetAttribute(gru_h<2>, cudaFuncAttributeMaxDynamicSharedMemorySize, SMEM_TOTAL);

    __half *gi16, *h16, *w16, *e16;
    cudaGetSymbolAddress((void**)&gi16, g_gi16);
    cudaGetSymbolAddress((void**)&h16,  g_h16);
    cudaGetSymbolAddress((void**)&w16,  g_w16);
    cudaGetSymbolAddress((void**)&e16,  g_e16);
    const size_t HN = (size_t)MB_ * HH_;

    dim3 grid(HH_ / BNG, MB_ / BM);   // (32, 64) = 2048 CTAs

    // convert enc + w_ih
    f2h_kernel<<<(MB_ * HH_ / 4 + 255) / 256, 256>>>(enc, e16, MB_ * HH_ / 4);
    f2h_kernel<<<(K3_ * HH_ / 4 + 255) / 256, 256>>>(w_ih, w16, K3_ * HH_ / 4);

    // gi = enc @ w_ih^T + b_ih  (fp16 store), fused with iteration 0 -> h16[0]
    gru_h<0><<<grid, NTH, SMEM_TOTAL>>>(e16, w16, b_ih, b_hh, gi16, nullptr, h16);

    // convert w_hh (stream-ordered after MODE0 consumed w_ih16)
    f2h_kernel<<<(K3_ * HH_ / 4 + 255) / 256, 256>>>(w_hh, w16, K3_ * HH_ / 4);

    // iterations 1..8 (write h16), iteration 9 (write fp32 out)
    int p = 0;
    for (int it = 1; it < NITER - 1; it++) {
        gru_h<1><<<grid, NTH, SMEM_TOTAL>>>(h16 + p * HN, w16, b_ih, b_hh, gi16,
                                            nullptr, h16 + (1 - p) * HN);
        p = 1 - p;
    }
    gru_h<2><<<grid, NTH, SMEM_TOTAL>>>(h16 + p * HN, w16, b_ih, b_hh, gi16, out, nullptr);
}

// round 9
// speedup vs baseline: 2.2811x; 1.0032x over previous
#include <cuda_runtime.h>
#include <cuda_fp16.h>
#include <cstdint>

// Problem constants (RecCore: B=8192, D=2048, H=2048, 10 iterations)
#define MB_  8192
#define HH_  2048
#define K3_  (3 * HH_)
#define NITER 10

#define BM 128
#define BNG 64                    // per-gate N tile
#define NSTK 192                  // stacked B rows (3 gates * 64)
#define BK 64                     // fp16 elems per chunk row = 128 bytes
#define NC 32                     // 2048 / 64
#define NTH 256
#define STAGE_BYTES ((BM + NSTK) * 128)   // 40960
#define SMEM_TOTAL (2 * STAGE_BYTES)      // 81920 -> 2 CTAs/SM

// Scratch
// gi interleaved: slot (m, n2) holds {r_h2, z_h2, n_h2, pad} = 16B; n2 = n/2 (0..1023)
__device__ uint4  g_gi[(long long)MB_ * (HH_ / 2)];
__device__ __half g_h16[2][(long long)MB_ * HH_];
__device__ __half g_w16i[(long long)K3_ * HH_];
__device__ __half g_w16h[(long long)K3_ * HH_];
__device__ __half g_e16[(long long)MB_ * HH_];

__device__ __forceinline__ uint32_t smem_u32(const void* p) {
    return (uint32_t)__cvta_generic_to_shared(p);
}
__device__ __forceinline__ void cp16(uint32_t s, const void* g) {
    asm volatile("cp.async.cg.shared.global [%0], [%1], 16;\n" :: "r"(s), "l"(g));
}
__device__ __forceinline__ float tanha(float x) {
    float y;
    asm("tanh.approx.f32 %0, %1;" : "=f"(y) : "f"(x));
    return y;
}
__device__ __forceinline__ float sigf(float x) {
    return 0.5f + 0.5f * tanha(0.5f * x);
}
__device__ __forceinline__ void ldsm4(uint32_t* r, uint32_t addr) {
    asm volatile("ldmatrix.sync.aligned.m8n8.x4.shared.b16 {%0,%1,%2,%3}, [%4];"
                 : "=r"(r[0]), "=r"(r[1]), "=r"(r[2]), "=r"(r[3]) : "r"(addr));
}
__device__ __forceinline__ void mma16816(float* c, const uint32_t* a, uint32_t b0, uint32_t b1) {
    asm volatile(
        "mma.sync.aligned.m16n8k16.row.col.f32.f16.f16.f32 "
        "{%0,%1,%2,%3}, {%4,%5,%6,%7}, {%8,%9}, {%0,%1,%2,%3};\n"
        : "+f"(c[0]), "+f"(c[1]), "+f"(c[2]), "+f"(c[3])
        : "r"(a[0]), "r"(a[1]), "r"(a[2]), "r"(a[3]), "r"(b0), "r"(b1));
}
__device__ __forceinline__ uint32_t swz(uint32_t off) {
    return off ^ ((off >> 3) & 0x70);
}
__device__ __forceinline__ uint32_t h2u(__half2 h) {
    return *reinterpret_cast<uint32_t*>(&h);
}
__device__ __forceinline__ __half2 u2h(uint32_t u) {
    return *reinterpret_cast<__half2*>(&u);
}

// Fused 3-gate fp16 GEMM (HMMA m16n8k16 + ldmatrix), fp32 accumulate.
// 256 threads, 2 CTAs/SM. Tile: M=128 x (64 per gate).
// MODE 0: gi (interleaved) = acc + b_ih  AND  h16 out = GRU step with h=0 (fused iter0)
// MODE 1: GRU step, intermediate: write h16 only
// MODE 2: GRU step, final: write fp32 out only
template <int MODE>
__global__ void __launch_bounds__(NTH, 2)
gru_h(const __half* __restrict__ A16,    // [8192, 2048]  (e16 or h16_in)
      const __half* __restrict__ W16,    // [6144, 2048]
      const float*  __restrict__ b_ih,   // [6144]  (MODE 0)
      const float*  __restrict__ b_hh,   // [6144]
      uint4*        __restrict__ gi,     // written MODE 0, read MODE 1/2
      float*        __restrict__ outf,   // MODE 2
      __half*       __restrict__ out16)  // MODE 0/1
{
    extern __shared__ char smc[];
    const uint32_t sbase = smem_u32(smc);
    const int t = threadIdx.x;
    const int wid = t >> 5, lane = t & 31;
    const int m0 = blockIdx.y * BM;
    const int n0 = blockIdx.x * BNG;
    const int wm  = (wid >> 1) * 32;     // warp m offset (0,32,64,96)
    const int wn2 = (wid & 1) * 32;      // warp n offset within gate (0,32)
    const int lr = lane >> 2;            // 0..7
    const int lc = lane & 3;             // 0..3

    float acc2[3][2][4][4];
#pragma unroll
    for (int g = 0; g < 3; g++)
#pragma unroll
        for (int i = 0; i < 2; i++)
#pragma unroll
            for (int j = 0; j < 4; j++)
#pragma unroll
                for (int c = 0; c < 4; c++) acc2[g][i][j][c] = 0.0f;

    // loader: 320 rows (A:0-127, W stacked:128-319) x 128B; 10 x 16B per thread
    auto issue = [&](int stage, int kc) {   // kc in fp16 elems
        uint32_t st = sbase + stage * STAGE_BYTES;
#pragma unroll
        for (int i = 0; i < 10; i++) {
            int id = t + NTH * i;          // 0..2559
            int row = id >> 3;             // 0..319
            int qb = (id & 7) * 16;        // byte offset in row
            const __half* gsrc;
            if (row < BM) {
                gsrc = A16 + (size_t)(m0 + row) * HH_ + kc + (qb >> 1);
            } else {
                int r = row - BM;
                int g = r >> 6, n = r & 63;
                gsrc = W16 + ((size_t)g * HH_ + n0 + n) * HH_ + kc + (qb >> 1);
            }
            cp16(st + swz(row * 128 + qb), gsrc);
        }
        asm volatile("cp.async.commit_group;\n" ::: "memory");
    };

    issue(0, 0);

    // ldmatrix lane addressing
    const int a_row = lane & 15;
    const int a_kb  = (lane >> 4) * 16;
    const int b_row = (lane & 7) | ((lane & 16) >> 1);
    const int b_kb  = (lane & 8) * 2;

    for (int c = 0; c < NC; c++) {
        asm volatile("cp.async.wait_group 0;\n" ::: "memory");
        __syncthreads();
        if (c + 1 < NC) issue((c + 1) & 1, (c + 1) * BK);

        uint32_t st = sbase + (c & 1) * STAGE_BYTES;

        auto aaddr = [&](int s, int i) {
            uint32_t off = (uint32_t)(wm + i * 16 + a_row) * 128 + s * 32 + a_kb;
            return st + swz(off);
        };
        auto baddr = [&](int s, int nx) {   // nx = g*2 + j2
            int g = nx >> 1, j2 = nx & 1;
            uint32_t off = (uint32_t)(BM + g * BNG + wn2 + j2 * 16 + b_row) * 128
                           + s * 32 + b_kb;
            return st + swz(off);
        };

        // fully-pipelined fragment stream across the 4 k16 steps
        uint32_t a[2][2][4];     // [s-slot][i][4]
        uint32_t b[2][4];
        ldsm4(a[0][0], aaddr(0, 0));
        ldsm4(a[0][1], aaddr(0, 1));
        ldsm4(b[0], baddr(0, 0));

#pragma unroll
        for (int s = 0; s < 4; s++) {
            const int cur = s & 1;
#pragma unroll
            for (int nx = 0; nx < 6; nx++) {
                const int bi = nx & 1;
                // prefetch next B fragment group (crossing step boundary)
                if (nx < 5)      ldsm4(b[bi ^ 1], baddr(s, nx + 1));
                else if (s < 3)  ldsm4(b[bi ^ 1], baddr(s + 1, 0));
                // prefetch A fragments for next step
                if (nx == 4 && s < 3) {
                    ldsm4(a[cur ^ 1][0], aaddr(s + 1, 0));
                    ldsm4(a[cur ^ 1][1], aaddr(s + 1, 1));
                }
                const int g = nx >> 1, j2 = nx & 1;
                mma16816(acc2[g][0][2 * j2],     a[cur][0], b[bi][0], b[bi][1]);
                mma16816(acc2[g][0][2 * j2 + 1], a[cur][0], b[bi][2], b[bi][3]);
                mma16816(acc2[g][1][2 * j2],     a[cur][1], b[bi][0], b[bi][1]);
                mma16816(acc2[g][1][2 * j2 + 1], a[cur][1], b[bi][2], b[bi][3]);
            }
        }
    }

    // ---------------- Epilogue ----------------
#pragma unroll
    for (int j = 0; j < 4; j++) {
        int ngl = n0 + wn2 + j * 8 + 2 * lc;     // global per-gate col (even)
        float2 bhr = *(const float2*)(b_hh + ngl);
        float2 bhz = *(const float2*)(b_hh + HH_ + ngl);
        float2 bhn = *(const float2*)(b_hh + 2 * HH_ + ngl);
        float2 bir, biz, bin;
        if (MODE == 0) {
            bir = *(const float2*)(b_ih + ngl);
            biz = *(const float2*)(b_ih + HH_ + ngl);
            bin = *(const float2*)(b_ih + 2 * HH_ + ngl);
        }
#pragma unroll
        for (int i = 0; i < 2; i++) {
            int m = m0 + wm + i * 16 + lr;
#pragma unroll
            for (int half = 0; half < 2; half++) {
                int mm = m + half * 8;
                int o  = half * 2;
                size_t slot = (size_t)mm * (HH_ / 2) + (ngl >> 1);

                if (MODE == 0) {
                    float grx = acc2[0][i][j][o]     + bir.x;
                    float gry = acc2[0][i][j][o + 1] + bir.y;
                    float gzx = acc2[1][i][j][o]     + biz.x;
                    float gzy = acc2[1][i][j][o + 1] + biz.y;
                    float gnx = acc2[2][i][j][o]     + bin.x;
                    float gny = acc2[2][i][j][o + 1] + bin.y;
                    uint4 v;
                    v.x = h2u(__floats2half2_rn(grx, gry));
                    v.y = h2u(__floats2half2_rn(gzx, gzy));
                    v.z = h2u(__floats2half2_rn(gnx, gny));
                    v.w = 0u;
                    gi[slot] = v;
                    // fused iteration 0 (h = 0)
                    float rx = sigf(grx + bhr.x), ry = sigf(gry + bhr.y);
                    float zx = sigf(gzx + bhz.x), zy = sigf(gzy + bhz.y);
                    float nx = tanha(gnx + rx * bhn.x);
                    float ny = tanha(gny + ry * bhn.y);
                    float hx = (1.0f - zx) * nx;
                    float hy = (1.0f - zy) * ny;
                    *(__half2*)(out16 + (size_t)mm * HH_ + ngl) = __floats2half2_rn(hx, hy);
                } else {
                    uint4 v = gi[slot];
                    float2 gr = __half22float2(u2h(v.x));
                    float2 gz = __half22float2(u2h(v.y));
                    float2 gn = __half22float2(u2h(v.z));
                    float2 hv = __half22float2(*(const __half2*)(A16 + (size_t)mm * HH_ + ngl));

                    float rx = sigf(gr.x + acc2[0][i][j][o]     + bhr.x);
                    float ry = sigf(gr.y + acc2[0][i][j][o + 1] + bhr.y);
                    float zx = sigf(gz.x + acc2[1][i][j][o]     + bhz.x);
                    float zy = sigf(gz.y + acc2[1][i][j][o + 1] + bhz.y);
                    float nx = tanha(gn.x + rx * (acc2[2][i][j][o]     + bhn.x));
                    float ny = tanha(gn.y + ry * (acc2[2][i][j][o + 1] + bhn.y));

                    float hx = nx + zx * (hv.x - nx);
                    float hy = ny + zy * (hv.y - ny);

                    if (MODE == 1) {
                        *(__half2*)(out16 + (size_t)mm * HH_ + ngl) = __floats2half2_rn(hx, hy);
                    } else {
                        *(float2*)(outf + (size_t)mm * HH_ + ngl) = make_float2(hx, hy);
                    }
                }
            }
        }
    }
}

// float -> half conversion (vectorized)
__global__ void f2h_kernel(const float* __restrict__ src, __half* __restrict__ dst, int n4)
{
    int i = blockIdx.x * blockDim.x + threadIdx.x;
    if (i < n4) {
        float4 v = ((const float4*)src)[i];
        ((__half2*)dst)[2 * i]     = __floats2half2_rn(v.x, v.y);
        ((__half2*)dst)[2 * i + 1] = __floats2half2_rn(v.z, v.w);
    }
}

extern "C" void kernel_launch(void* const* d_in, const int* in_sizes, int n_in,
                              void* d_out, int out_size)
{
    const float* enc  = (const float*)d_in[0];
    const float* w_ih = (const float*)d_in[1];
    const float* w_hh = (const float*)d_in[2];
    const float* b_ih = (const float*)d_in[3];
    const float* b_hh = (const float*)d_in[4];
    float* out = (float*)d_out;

    cudaFuncSetAttribute(gru_h<0>, cudaFuncAttributeMaxDynamicSharedMemorySize, SMEM_TOTAL);
    cudaFuncSetAttribute(gru_h<1>, cudaFuncAttributeMaxDynamicSharedMemorySize, SMEM_TOTAL);
    cudaFuncSetAttribute(gru_h<2>, cudaFuncAttributeMaxDynamicSharedMemorySize, SMEM_TOTAL);

    uint4* gi;
    __half *h16, *w16i, *w16h, *e16;
    cudaGetSymbolAddress((void**)&gi,   g_gi);
    cudaGetSymbolAddress((void**)&h16,  g_h16);
    cudaGetSymbolAddress((void**)&w16i, g_w16i);
    cudaGetSymbolAddress((void**)&w16h, g_w16h);
    cudaGetSymbolAddress((void**)&e16,  g_e16);
    const size_t HN = (size_t)MB_ * HH_;

    dim3 grid(HH_ / BNG, MB_ / BM);   // (32, 64) = 2048 CTAs

    // convert all operands upfront
    f2h_kernel<<<(MB_ * HH_ / 4 + 255) / 256, 256>>>(enc, e16, MB_ * HH_ / 4);
    f2h_kernel<<<(K3_ * HH_ / 4 + 255) / 256, 256>>>(w_ih, w16i, K3_ * HH_ / 4);
    f2h_kernel<<<(K3_ * HH_ / 4 + 255) / 256, 256>>>(w_hh, w16h, K3_ * HH_ / 4);

    // gi = enc @ w_ih^T + b_ih  (interleaved fp16), fused with iteration 0 -> h16[0]
    gru_h<0><<<grid, NTH, SMEM_TOTAL>>>(e16, w16i, b_ih, b_hh, gi, nullptr, h16);

    // iterations 1..8 (write h16), iteration 9 (write fp32 out)
    int p = 0;
    for (int it = 1; it < NITER - 1; it++) {
        gru_h<1><<<grid, NTH, SMEM_TOTAL>>>(h16 + p * HN, w16h, b_ih, b_hh, gi,
                                            nullptr, h16 + (1 - p) * HN);
        p = 1 - p;
    }
    gru_h<2><<<grid, NTH, SMEM_TOTAL>>>(h16 + p * HN, w16h, b_ih, b_hh, gi, out, nullptr);
}

// round 10
// speedup vs baseline: 2.2938x; 1.0056x over previous
#include <cuda_runtime.h>
#include <cuda_fp16.h>
#include <cstdint>

// Problem constants (RecCore: B=8192, D=2048, H=2048, 10 iterations)
#define MB_  8192
#define HH_  2048
#define K3_  (3 * HH_)
#define NITER 10

#define BM 128
#define BNG 64                    // per-gate N tile
#define NSTK 192                  // stacked B rows (3 gates * 64)
#define BK 64                     // fp16 elems per chunk row = 128 bytes
#define NC 32                     // 2048 / 64
#define NTH 256
#define STAGE_BYTES ((BM + NSTK) * 128)   // 40960
#define SMEM_TOTAL (2 * STAGE_BYTES)      // 81920 -> 2 CTAs/SM

// Scratch
// gi interleaved: slot (m, n2) holds {r_h2, z_h2, n_h2, pad} = 16B; n2 = n/2 (0..1023)
__device__ uint4  g_gi[(long long)MB_ * (HH_ / 2)];
__device__ __half g_h16[2][(long long)MB_ * HH_];
__device__ __half g_w16i[(long long)K3_ * HH_];
__device__ __half g_w16h[(long long)K3_ * HH_];
__device__ __half g_e16[(long long)MB_ * HH_];

__device__ __forceinline__ uint32_t smem_u32(const void* p) {
    return (uint32_t)__cvta_generic_to_shared(p);
}
__device__ __forceinline__ void cp16(uint32_t s, const void* g) {
    asm volatile("cp.async.cg.shared.global [%0], [%1], 16;\n" :: "r"(s), "l"(g));
}
__device__ __forceinline__ float tanha(float x) {
    float y;
    asm("tanh.approx.f32 %0, %1;" : "=f"(y) : "f"(x));
    return y;
}
__device__ __forceinline__ float sigf(float x) {
    return 0.5f + 0.5f * tanha(0.5f * x);
}
__device__ __forceinline__ void ldsm4(uint32_t* r, uint32_t addr) {
    asm volatile("ldmatrix.sync.aligned.m8n8.x4.shared.b16 {%0,%1,%2,%3}, [%4];"
                 : "=r"(r[0]), "=r"(r[1]), "=r"(r[2]), "=r"(r[3]) : "r"(addr));
}
__device__ __forceinline__ void mma16816(float* c, const uint32_t* a, uint32_t b0, uint32_t b1) {
    asm volatile(
        "mma.sync.aligned.m16n8k16.row.col.f32.f16.f16.f32 "
        "{%0,%1,%2,%3}, {%4,%5,%6,%7}, {%8,%9}, {%0,%1,%2,%3};\n"
        : "+f"(c[0]), "+f"(c[1]), "+f"(c[2]), "+f"(c[3])
        : "r"(a[0]), "r"(a[1]), "r"(a[2]), "r"(a[3]), "r"(b0), "r"(b1));
}
__device__ __forceinline__ uint32_t swz(uint32_t off) {
    return off ^ ((off >> 3) & 0x70);
}
__device__ __forceinline__ uint32_t h2u(__half2 h) {
    return *reinterpret_cast<uint32_t*>(&h);
}
__device__ __forceinline__ __half2 u2h(uint32_t u) {
    return *reinterpret_cast<__half2*>(&u);
}
__device__ __forceinline__ void pfL2(const void* p) {
    asm volatile("prefetch.global.L2 [%0];" :: "l"(p));
}

// Fused 3-gate fp16 GEMM (HMMA m16n8k16 + ldmatrix), fp32 accumulate.
// 256 threads, 2 CTAs/SM. Tile: M=128 x (64 per gate).
// MODE 0: gi (interleaved) = acc + b_ih  AND  h16 out = GRU step with h=0 (fused iter0)
// MODE 1: GRU step, intermediate: write h16 only
// MODE 2: GRU step, final: write fp32 out only
template <int MODE>
__global__ void __launch_bounds__(NTH, 2)
gru_h(const __half* __restrict__ A16,    // [8192, 2048]  (e16 or h16_in)
      const __half* __restrict__ W16,    // [6144, 2048]
      const float*  __restrict__ b_ih,   // [6144]  (MODE 0)
      const float*  __restrict__ b_hh,   // [6144]
      uint4*        __restrict__ gi,     // written MODE 0, read MODE 1/2
      float*        __restrict__ outf,   // MODE 2
      __half*       __restrict__ out16)  // MODE 0/1
{
    extern __shared__ char smc[];
    const uint32_t sbase = smem_u32(smc);
    const int t = threadIdx.x;
    const int wid = t >> 5, lane = t & 31;
    const int m0 = blockIdx.y * BM;
    const int n0 = blockIdx.x * BNG;
    const int wm  = (wid >> 1) * 32;     // warp m offset (0,32,64,96)
    const int wn2 = (wid & 1) * 32;      // warp n offset within gate (0,32)
    const int lr = lane >> 2;            // 0..7
    const int lc = lane & 3;             // 0..3

    float acc2[3][2][4][4];
#pragma unroll
    for (int g = 0; g < 3; g++)
#pragma unroll
        for (int i = 0; i < 2; i++)
#pragma unroll
            for (int j = 0; j < 4; j++)
#pragma unroll
                for (int c = 0; c < 4; c++) acc2[g][i][j][c] = 0.0f;

    // loader: 320 rows (A:0-127, W stacked:128-319) x 128B; 10 x 16B per thread
    auto issue = [&](int stage, int kc) {   // kc in fp16 elems
        uint32_t st = sbase + stage * STAGE_BYTES;
#pragma unroll
        for (int i = 0; i < 10; i++) {
            int id = t + NTH * i;          // 0..2559
            int row = id >> 3;             // 0..319
            int qb = (id & 7) * 16;        // byte offset in row
            const __half* gsrc;
            if (row < BM) {
                gsrc = A16 + (size_t)(m0 + row) * HH_ + kc + (qb >> 1);
            } else {
                int r = row - BM;
                int g = r >> 6, n = r & 63;
                gsrc = W16 + ((size_t)g * HH_ + n0 + n) * HH_ + kc + (qb >> 1);
            }
            cp16(st + swz(row * 128 + qb), gsrc);
        }
        asm volatile("cp.async.commit_group;\n" ::: "memory");
    };

    issue(0, 0);

    // ldmatrix lane addressing
    const int a_row = lane & 15;
    const int a_kb  = (lane >> 4) * 16;
    const int b_row = (lane & 7) | ((lane & 16) >> 1);
    const int b_kb  = (lane & 8) * 2;

    for (int c = 0; c < NC; c++) {
        asm volatile("cp.async.wait_group 0;\n" ::: "memory");
        __syncthreads();

        // L2 prefetch of epilogue operands, issued once, well before the tail
        if (MODE != 0 && c == NC - 4) {
#pragma unroll
            for (int j = 0; j < 4; j++) {
                int ngl = n0 + wn2 + j * 8 + 2 * lc;
#pragma unroll
                for (int i = 0; i < 2; i++) {
                    int m = m0 + wm + i * 16 + lr;
#pragma unroll
                    for (int half = 0; half < 2; half++) {
                        int mm = m + half * 8;
                        pfL2(gi + (size_t)mm * (HH_ / 2) + (ngl >> 1));
                        pfL2(A16 + (size_t)mm * HH_ + ngl);
                    }
                }
            }
        }

        uint32_t st = sbase + (c & 1) * STAGE_BYTES;

        auto aaddr = [&](int s, int i) {
            uint32_t off = (uint32_t)(wm + i * 16 + a_row) * 128 + s * 32 + a_kb;
            return st + swz(off);
        };
        auto baddr = [&](int s, int nx) {   // nx = g*2 + j2
            int g = nx >> 1, j2 = nx & 1;
            uint32_t off = (uint32_t)(BM + g * BNG + wn2 + j2 * 16 + b_row) * 128
                           + s * 32 + b_kb;
            return st + swz(off);
        };

        // fully-pipelined fragment stream across the 4 k16 steps
        uint32_t a[2][2][4];     // [s-slot][i][4]
        uint32_t b[2][4];
        ldsm4(a[0][0], aaddr(0, 0));
        ldsm4(a[0][1], aaddr(0, 1));
        ldsm4(b[0], baddr(0, 0));

#pragma unroll
        for (int s = 0; s < 4; s++) {
            const int cur = s & 1;
#pragma unroll
            for (int nx = 0; nx < 6; nx++) {
                const int bi = nx & 1;
                // prefetch next B fragment group (crossing step boundary)
                if (nx < 5)      ldsm4(b[bi ^ 1], baddr(s, nx + 1));
                else if (s < 3)  ldsm4(b[bi ^ 1], baddr(s + 1, 0));
                // prefetch A fragments for next step
                if (nx == 4 && s < 3) {
                    ldsm4(a[cur ^ 1][0], aaddr(s + 1, 0));
                    ldsm4(a[cur ^ 1][1], aaddr(s + 1, 1));
                }
                const int g = nx >> 1, j2 = nx & 1;
                mma16816(acc2[g][0][2 * j2],     a[cur][0], b[bi][0], b[bi][1]);
                mma16816(acc2[g][0][2 * j2 + 1], a[cur][0], b[bi][2], b[bi][3]);
                mma16816(acc2[g][1][2 * j2],     a[cur][1], b[bi][0], b[bi][1]);
                mma16816(acc2[g][1][2 * j2 + 1], a[cur][1], b[bi][2], b[bi][3]);
            }
            // overlap the next chunk's cp.async issue burst with the MMA stream
            if (s == 0 && c + 1 < NC) issue((c + 1) & 1, (c + 1) * BK);
        }
    }

    // ---------------- Epilogue ----------------
#pragma unroll
    for (int j = 0; j < 4; j++) {
        int ngl = n0 + wn2 + j * 8 + 2 * lc;     // global per-gate col (even)
        float2 bhr = *(const float2*)(b_hh + ngl);
        float2 bhz = *(const float2*)(b_hh + HH_ + ngl);
        float2 bhn = *(const float2*)(b_hh + 2 * HH_ + ngl);
        float2 bir, biz, bin;
        if (MODE == 0) {
            bir = *(const float2*)(b_ih + ngl);
            biz = *(const float2*)(b_ih + HH_ + ngl);
            bin = *(const float2*)(b_ih + 2 * HH_ + ngl);
        }
#pragma unroll
        for (int i = 0; i < 2; i++) {
            int m = m0 + wm + i * 16 + lr;
#pragma unroll
            for (int half = 0; half < 2; half++) {
                int mm = m + half * 8;
                int o  = half * 2;
                size_t slot = (size_t)mm * (HH_ / 2) + (ngl >> 1);

                if (MODE == 0) {
                    float grx = acc2[0][i][j][o]     + bir.x;
                    float gry = acc2[0][i][j][o + 1] + bir.y;
                    float gzx = acc2[1][i][j][o]     + biz.x;
                    float gzy = acc2[1][i][j][o + 1] + biz.y;
                    float gnx = acc2[2][i][j][o]     + bin.x;
                    float gny = acc2[2][i][j][o + 1] + bin.y;
                    uint4 v;
                    v.x = h2u(__floats2half2_rn(grx, gry));
                    v.y = h2u(__floats2half2_rn(gzx, gzy));
                    v.z = h2u(__floats2half2_rn(gnx, gny));
                    v.w = 0u;
                    gi[slot] = v;
                    // fused iteration 0 (h = 0)
                    float rx = sigf(grx + bhr.x), ry = sigf(gry + bhr.y);
                    float zx = sigf(gzx + bhz.x), zy = sigf(gzy + bhz.y);
                    float nx = tanha(gnx + rx * bhn.x);
                    float ny = tanha(gny + ry * bhn.y);
                    float hx = (1.0f - zx) * nx;
                    float hy = (1.0f - zy) * ny;
                    *(__half2*)(out16 + (size_t)mm * HH_ + ngl) = __floats2half2_rn(hx, hy);
                } else {
                    uint4 v = gi[slot];
                    float2 gr = __half22float2(u2h(v.x));
                    float2 gz = __half22float2(u2h(v.y));
                    float2 gn = __half22float2(u2h(v.z));
                    float2 hv = __half22float2(*(const __half2*)(A16 + (size_t)mm * HH_ + ngl));

                    float rx = sigf(gr.x + acc2[0][i][j][o]     + bhr.x);
                    float ry = sigf(gr.y + acc2[0][i][j][o + 1] + bhr.y);
                    float zx = sigf(gz.x + acc2[1][i][j][o]     + bhz.x);
                    float zy = sigf(gz.y + acc2[1][i][j][o + 1] + bhz.y);
                    float nx = tanha(gn.x + rx * (acc2[2][i][j][o]     + bhn.x));
                    float ny = tanha(gn.y + ry * (acc2[2][i][j][o + 1] + bhn.y));

                    float hx = nx + zx * (hv.x - nx);
                    float hy = ny + zy * (hv.y - ny);

                    if (MODE == 1) {
                        *(__half2*)(out16 + (size_t)mm * HH_ + ngl) = __floats2half2_rn(hx, hy);
                    } else {
                        *(float2*)(outf + (size_t)mm * HH_ + ngl) = make_float2(hx, hy);
                    }
                }
            }
        }
    }
}

// float -> half conversion (vectorized)
__global__ void f2h_kernel(const float* __restrict__ src, __half* __restrict__ dst, int n4)
{
    int i = blockIdx.x * blockDim.x + threadIdx.x;
    if (i < n4) {
        float4 v = ((const float4*)src)[i];
        ((__half2*)dst)[2 * i]     = __floats2half2_rn(v.x, v.y);
        ((__half2*)dst)[2 * i + 1] = __floats2half2_rn(v.z, v.w);
    }
}

extern "C" void kernel_launch(void* const* d_in, const int* in_sizes, int n_in,
                              void* d_out, int out_size)
{
    const float* enc  = (const float*)d_in[0];
    const float* w_ih = (const float*)d_in[1];
    const float* w_hh = (const float*)d_in[2];
    const float* b_ih = (const float*)d_in[3];
    const float* b_hh = (const float*)d_in[4];
    float* out = (float*)d_out;

    cudaFuncSetAttribute(gru_h<0>, cudaFuncAttributeMaxDynamicSharedMemorySize, SMEM_TOTAL);
    cudaFuncSetAttribute(gru_h<1>, cudaFuncAttributeMaxDynamicSharedMemorySize, SMEM_TOTAL);
    cudaFuncSetAttribute(gru_h<2>, cudaFuncAttributeMaxDynamicSharedMemorySize, SMEM_TOTAL);

    uint4* gi;
    __half *h16, *w16i, *w16h, *e16;
    cudaGetSymbolAddress((void**)&gi,   g_gi);
    cudaGetSymbolAddress((void**)&h16,  g_h16);
    cudaGetSymbolAddress((void**)&w16i, g_w16i);
    cudaGetSymbolAddress((void**)&w16h, g_w16h);
    cudaGetSymbolAddress((void**)&e16,  g_e16);
    const size_t HN = (size_t)MB_ * HH_;

    dim3 grid(HH_ / BNG, MB_ / BM);   // (32, 64) = 2048 CTAs

    // convert all operands upfront
    f2h_kernel<<<(MB_ * HH_ / 4 + 255) / 256, 256>>>(enc, e16, MB_ * HH_ / 4);
    f2h_kernel<<<(K3_ * HH_ / 4 + 255) / 256, 256>>>(w_ih, w16i, K3_ * HH_ / 4);
    f2h_kernel<<<(K3_ * HH_ / 4 + 255) / 256, 256>>>(w_hh, w16h, K3_ * HH_ / 4);

    // gi = enc @ w_ih^T + b_ih  (interleaved fp16), fused with iteration 0 -> h16[0]
    gru_h<0><<<grid, NTH, SMEM_TOTAL>>>(e16, w16i, b_ih, b_hh, gi, nullptr, h16);

    // iterations 1..8 (write h16), iteration 9 (write fp32 out)
    int p = 0;
    for (int it = 1; it < NITER - 1; it++) {
        gru_h<1><<<grid, NTH, SMEM_TOTAL>>>(h16 + p * HN, w16h, b_ih, b_hh, gi,
                                            nullptr, h16 + (1 - p) * HN);
        p = 1 - p;
    }
    gru_h<2><<<grid, NTH, SMEM_TOTAL>>>(h16 + p * HN, w16h, b_ih, b_hh, gi, out, nullptr);
}